// round 12
// baseline (speedup 1.0000x reference)
#include <cuda_runtime.h>
#include <cuda_fp16.h>
#include <cstdint>
#include <cstddef>

#define BB   64
#define TT   256
#define DD   1024
#define HH   1024
#define G4   4096
#define NB   128

// ---------------- device scratch ----------------
__device__ __align__(256) float  g_G0p[(size_t)TT * NB * 64 * 32]; // [t][bn][row64][gate8*4] fp32
__device__ __align__(256) __half g_Xh[(size_t)BB * TT * DD];       // fp16 X, row-major
__device__ __align__(256) __half g_Wx0h[DD * G4];                  // fp16 col-major [col][k]
__device__ __align__(256) __half g_Wh0h[HH * G4];    // fp16 swizzled tiles [bn][ii8][col32][kin128]
__device__ __align__(256) __half g_Wx1h[HH * G4];
__device__ __align__(256) __half g_Wh1h[HH * G4];
__device__ float  g_b1p[NB * 32];
__device__ __align__(256) __half g_h0h[2][BB * HH];  // fp16 swizzled k-tiles [ii8][row64][kin128]
__device__ __align__(256) __half g_h1h[2][BB * HH];
__device__ float  g_h1e[BB * HH];
__device__ unsigned g_bar0;   // h0-ready arrivals
__device__ unsigned g_bar1;   // h1-ready arrivals

// ---------------- smem layout (bytes) ----------------
// 4 stages x 32768 | dump 73728 | G0 8192 | mbars
#define STAGE_SZ  32768
#define NSTG      4
#define DUMP_OFF  131072
#define G0_OFF    204800
#define MB_OFF    212992
#define SMEM_BYTES 213248

// ---------------- helpers ----------------
__device__ __forceinline__ void mma_f16(float* d, const uint32_t* a, const uint32_t* b) {
    asm volatile(
        "mma.sync.aligned.m16n8k16.row.col.f32.f16.f16.f32 "
        "{%0,%1,%2,%3}, {%4,%5,%6,%7}, {%8,%9}, {%0,%1,%2,%3};"
        : "+f"(d[0]), "+f"(d[1]), "+f"(d[2]), "+f"(d[3])
        : "r"(a[0]), "r"(a[1]), "r"(a[2]), "r"(a[3]), "r"(b[0]), "r"(b[1]));
}
__device__ __forceinline__ void ldsm4(uint32_t* r, uint32_t addr) {
    asm volatile("ldmatrix.sync.aligned.m8n8.x4.shared.b16 {%0,%1,%2,%3}, [%4];"
        : "=r"(r[0]), "=r"(r[1]), "=r"(r[2]), "=r"(r[3]) : "r"(addr));
}
__device__ __forceinline__ void cp16(uint32_t s, const void* g) {
    asm volatile("cp.async.cg.shared.global [%0], [%1], 16;" :: "r"(s), "l"(g));
}
#define CP_COMMIT() asm volatile("cp.async.commit_group;")
#define CP_WAIT1()  asm volatile("cp.async.wait_group 1;")

__device__ __forceinline__ void mbar_init(uint32_t a, uint32_t cnt) {
    asm volatile("mbarrier.init.shared.b64 [%0], %1;" :: "r"(a), "r"(cnt) : "memory");
}
__device__ __forceinline__ void mbar_expect(uint32_t a, uint32_t tx) {
    asm volatile("mbarrier.arrive.expect_tx.shared.b64 _, [%0], %1;" :: "r"(a), "r"(tx) : "memory");
}
__device__ __forceinline__ void bulkcp(uint32_t dst, const void* src, uint32_t sz, uint32_t mb) {
    asm volatile(
        "cp.async.bulk.shared::cluster.global.mbarrier::complete_tx::bytes [%0], [%1], %2, [%3];"
        :: "r"(dst), "l"(src), "r"(sz), "r"(mb) : "memory");
}
__device__ __forceinline__ void mbar_wait(uint32_t a, uint32_t par) {
    asm volatile(
        "{\n\t.reg .pred P;\n\tWAIT%=:\n\t"
        "mbarrier.try_wait.parity.acquire.cta.shared::cta.b64 P, [%0], %1;\n\t"
        "@!P bra WAIT%=;\n\t}"
        :: "r"(a), "r"(par) : "memory");
}

__device__ __forceinline__ float sigf(float x)   { return 1.f / (1.f + __expf(-x)); }
__device__ __forceinline__ float tanhf_(float x) { return 2.f / (1.f + __expf(-2.f * x)) - 1.f; }

// ---------------- convert + pack ----------------
__global__ void convert_pack_kernel(const float* __restrict__ x,
                                    const float* __restrict__ Wx0, const float* __restrict__ Wh0,
                                    const float* __restrict__ Wx1, const float* __restrict__ Wh1,
                                    const float* __restrict__ b1) {
    const int n1 = 1 << 22;
    const int stride = gridDim.x * blockDim.x;
    for (int idx = blockIdx.x * blockDim.x + threadIdx.x; idx < 4 * n1; idx += stride) {
        int w = idx >> 22;
        int d = idx & (n1 - 1);
        if (w == 0) {
            int k = d & 1023, col = d >> 10;
            g_Wx0h[d] = __float2half_rn(Wx0[(size_t)k * G4 + col]);  // col-major
        } else {
            int kin = d & 127, col = (d >> 7) & 31, ii = (d >> 12) & 7, bq = d >> 15;
            int gate = col >> 3, cw = col & 7;
            int k = ii * 128 + kin;
            int src = k * G4 + gate * HH + bq * 8 + cw;
            float v = (w == 1) ? Wh0[src] : (w == 2) ? Wx1[src] : Wh1[src];
            uint32_t off = (uint32_t)col * 256 + (uint32_t)kin * 2;
            uint32_t sw = off ^ ((off >> 4) & 0x70);
            __half* dst = (w == 1) ? g_Wh0h : (w == 2) ? g_Wx1h : g_Wh1h;
            dst[(size_t)(bq * 8 + ii) * 4096 + (sw >> 1)] = __float2half_rn(v);
        }
    }
    for (size_t i = blockIdx.x * blockDim.x + threadIdx.x; i < (size_t)BB * TT * DD; i += stride)
        g_Xh[i] = __float2half_rn(x[i]);
    for (int i = blockIdx.x * blockDim.x + threadIdx.x; i < NB * 32; i += stride) {
        int bn = i >> 5, c = i & 31, gate = c >> 3, cw = c & 7;
        g_b1p[i] = b1[gate * HH + bn * 8 + cw];
    }
}

__global__ void init_kernel() {
    int i = blockIdx.x * blockDim.x + threadIdx.x;
    if (i < BB * HH) {
        g_h0h[0][i] = __float2half(0.f); g_h0h[1][i] = __float2half(0.f);
        g_h1h[0][i] = __float2half(0.f); g_h1h[1][i] = __float2half(0.f);
    }
    if (i == 0) { g_bar0 = 0u; g_bar1 = 0u; }
}

// ---------------- precompute G0 = X @ Wx0 + b0 (fp16 HMMA) ----------------
#define XSTAGE 15360
#define XSMEM  (3 * XSTAGE)

__global__ void __launch_bounds__(256, 2) xgemm_kernel(const float* __restrict__ b0) {
    extern __shared__ float xsm[];
    uint32_t sb = (uint32_t)__cvta_generic_to_shared(xsm);
    const int tid = threadIdx.x, lane = tid & 31, warp = tid >> 5;
    const int wm = warp & 3, wn = warp >> 2;
    const int bm = blockIdx.y * 128;
    const int bn = blockIdx.x * 64;

    uint32_t dstA[2], srcA[2];
#pragma unroll
    for (int j = 0; j < 2; j++) {
        int c = j * 256 + tid, row = c >> 2, kc = c & 3;
        dstA[j] = row * 80u + kc * 16u;
        srcA[j] = (uint32_t)((bm + row) * 2048 + kc * 16);
    }
    uint32_t dstB, srcB;
    {
        int col = tid >> 2, kc = tid & 3;
        dstB = 10240u + col * 80u + kc * 16u;
        srcB = (uint32_t)((bn + col) * 2048 + kc * 16);
    }
    const uint32_t laneoffA = (wm * 32 + (lane & 15)) * 80u + (lane >> 4) * 16u;
    const uint32_t laneoffB = 10240u + (wn * 32 + ((lane >> 4) << 3) + (lane & 7)) * 80u
                              + ((lane >> 3) & 1) * 16u;

    auto issue = [&](int st, int k0) {
        const uint32_t stb = sb + st * XSTAGE;
        const char* xb = (const char*)g_Xh + (size_t)k0 * 2;
        const char* wb = (const char*)g_Wx0h + (size_t)k0 * 2;
#pragma unroll
        for (int j = 0; j < 2; j++) cp16(stb + dstA[j], xb + srcA[j]);
        cp16(stb + dstB, wb + srcB);
    };

    float acc[2][4][4];
#pragma unroll
    for (int m = 0; m < 2; m++)
#pragma unroll
        for (int n = 0; n < 4; n++)
#pragma unroll
            for (int p = 0; p < 4; p++) acc[m][n][p] = 0.f;

    issue(0, 0); CP_COMMIT();
    issue(1, 32); CP_COMMIT();

    int st = 0, st2 = 2;
    for (int it = 0; it < 32; it++) {
        CP_WAIT1();
        __syncthreads();
        if (it + 2 < 32) issue(st2, (it + 2) * 32);
        CP_COMMIT();

        const uint32_t base = sb + st * XSTAGE;
#pragma unroll
        for (int ks = 0; ks < 2; ks++) {
            uint32_t a0[4], a1[4], b01[4], b23[4];
            ldsm4(a0, base + laneoffA + ks * 32);
            ldsm4(a1, base + laneoffA + 1280 + ks * 32);
            ldsm4(b01, base + laneoffB + ks * 32);
            ldsm4(b23, base + laneoffB + 1280 + ks * 32);
            mma_f16(acc[0][0], a0, b01);     mma_f16(acc[1][0], a1, b01);
            mma_f16(acc[0][1], a0, b01 + 2); mma_f16(acc[1][1], a1, b01 + 2);
            mma_f16(acc[0][2], a0, b23);     mma_f16(acc[1][2], a1, b23);
            mma_f16(acc[0][3], a0, b23 + 2); mma_f16(acc[1][3], a1, b23 + 2);
        }
        st = (st == 2) ? 0 : st + 1;
        st2 = (st2 == 2) ? 0 : st2 + 1;
    }

#pragma unroll
    for (int mt = 0; mt < 2; mt++)
#pragma unroll
        for (int nt = 0; nt < 4; nt++)
#pragma unroll
            for (int p = 0; p < 4; p++) {
                int row = bm + wm * 32 + mt * 16 + (lane >> 2) + ((p & 2) ? 8 : 0);
                int col = bn + wn * 32 + nt * 8 + 2 * (lane & 3) + (p & 1);
                int b_ = row >> 8;
                int t_ = row & 255;
                int gate = col >> 10, within = col & 1023;
                int bnp = within >> 3, cwi = within & 7;
                g_G0p[(((size_t)t_ * NB + bnp) * 64 + b_) * 32 + gate * 8 + cwi] =
                    acc[mt][nt][p] + __ldg(&b0[col]);
            }
}

// ---------------- persistent merged recurrence (split-barrier, 4-stage) ----------------
__global__ void __launch_bounds__(512, 1) lstm_persist() {
    extern __shared__ float sm[];
    uint32_t sb = (uint32_t)__cvta_generic_to_shared(sm);
    const int tid = threadIdx.x, lane = tid & 31, warp = tid >> 5;
    const int wk = warp & 7, wm = warp >> 3;
    const int bn = blockIdx.x;
    const int erow = tid >> 3, ecw = tid & 7;

    const uint32_t mb0   = sb + MB_OFF;
    const uint32_t mb_g0 = sb + MB_OFF + NSTG * 8;
    if (tid == 0) {
#pragma unroll
        for (int i = 0; i < NSTG; i++) mbar_init(mb0 + i * 8, 2);
        mbar_init(mb_g0, 1);
    }
    __syncthreads();

    // ldmatrix lane offsets (swizzled, 256B row stride, k-window = wk*32 bytes)
    const uint32_t kbA = (uint32_t)wk * 32 + (uint32_t)(lane >> 4) * 16;
    const uint32_t laneA = (uint32_t)(wm * 32 + (lane & 15)) * 256
                           + (kbA ^ (((uint32_t)lane & 7) << 4));
    const uint32_t kbB = (uint32_t)wk * 32 + (uint32_t)((lane >> 3) & 1) * 16;
    const uint32_t laneB = 16384u + (uint32_t)(((lane >> 4) << 3) + (lane & 7)) * 256
                           + (kbB ^ (((uint32_t)lane & 7) << 4));

    const char* W0base = (const char*)g_Wh0h + (size_t)bn * 65536;
    const char* W1base = (const char*)g_Wx1h + (size_t)bn * 65536;
    const char* W2base = (const char*)g_Wh1h + (size_t)bn * 65536;

    auto fillB = [&](int st, int fi) {
        const uint32_t mb = mb0 + st * 8;
        const int seg = fi >> 3, ii = fi & 7;
        const uint32_t d = sb + st * STAGE_SZ + 16384;
        if (seg) {
            mbar_expect(mb, 8192);
            bulkcp(d, W2base + ii * 8192, 8192, mb);
        } else {
            mbar_expect(mb, 16384);
            bulkcp(d,        W0base + ii * 8192, 8192, mb);
            bulkcp(d + 8192, W1base + ii * 8192, 8192, mb);
        }
    };
    auto fillA = [&](int st, int fi, const char* A0p, const char* A1p) {
        const uint32_t mb = mb0 + st * 8;
        const int seg = fi >> 3, ii = fi & 7;
        const char* src = (seg ? A1p : A0p) + ii * 16384;
        const uint32_t d = sb + st * STAGE_SZ;
        mbar_expect(mb, 16384);
        bulkcp(d,        src,        8192, mb);
        bulkcp(d + 8192, src + 8192, 8192, mb);
    };
    auto fillG0 = [&](int t) {
        mbar_expect(mb_g0, 8192);
        bulkcp(sb + G0_OFF, (const char*)g_G0p + ((size_t)t * NB + bn) * 8192, 8192, mb_g0);
    };

    // epilogue h-store swizzled address
    const int iiH = bn >> 4;
    const int kinH = (bn & 15) * 8 + ecw;
    const uint32_t offH = (uint32_t)erow * 256 + (uint32_t)kinH * 2;
    const uint32_t swH = offH ^ ((offH >> 4) & 0x70);
    const int physH = iiH * 8192 + (int)(swH >> 1);

    float* dmp = sm + (DUMP_OFF >> 2);
    const float* g0f = sm + (G0_OFF >> 2);

    float c0r = 0.f, c1r = 0.f;
    unsigned pb = 0;

    // initial fills: iters 0-2 (stages 0-2) + G0(0)
    if (tid == 0) {
        const char* A0i = (const char*)g_h0h[0];
        fillG0(0);
#pragma unroll
        for (int j = 0; j < 3; j++) { fillA(j, j, A0i, A0i); fillB(j, j); }
    }

    for (int s = 0; s <= 256; s++) {
        const char* A0 = (const char*)g_h0h[s & 1];
        const char* A1 = (const char*)g_h1h[(s + 1) & 1];
        const char* A0n = (const char*)g_h0h[(s + 1) & 1];

        float acc0[2][4][4], acc1[2][4][4];
#pragma unroll
        for (int m = 0; m < 2; m++)
#pragma unroll
            for (int n = 0; n < 4; n++)
#pragma unroll
                for (int p = 0; p < 4; p++) { acc0[m][n][p] = 0.f; acc1[m][n][p] = 0.f; }

#pragma unroll
        for (int i = 0; i < 16; i++) {
            const int stc = i & 3;
            mbar_wait(mb0 + stc * 8, (pb >> stc) & 1);
            pb ^= 1u << stc;
            __syncthreads();

            if (tid == 0) {
                if (i == 5 && s > 0) {   // gate A1 fills on h1[s] from all blocks
                    while (*(volatile unsigned*)&g_bar1 < (unsigned)s * NB) {}
                    __threadfence();
                }
                const int ft = i + 3;
                if (ft < 16) {
                    fillA(ft & 3, ft, A0, A1);
                    fillB(ft & 3, ft);
                } else if (s < 256) {
                    if (i == 13) {       // gate next-superstep A0 fills on h0[s+1]
                        while (*(volatile unsigned*)&g_bar0 < (unsigned)(s + 1) * NB) {}
                        __threadfence();
                    }
                    fillA(ft & 3, ft - 16, A0n, A0n);   // ft-16 in 0..2 => seg0, A1 unused
                    fillB(ft & 3, ft - 16);
                }
            }

            const uint32_t stgb = sb + stc * STAGE_SZ;
            const int seg = i >> 3;
            uint32_t a0[4], a1[4], b0[4], b1r[4];
            ldsm4(a0, stgb + laneA);
            ldsm4(a1, stgb + laneA + 4096);
            ldsm4(b0, stgb + laneB);
            ldsm4(b1r, stgb + laneB + 4096);
            if (seg) {
                mma_f16(acc1[0][0], a0, b0);      mma_f16(acc1[1][0], a1, b0);
                mma_f16(acc1[0][1], a0, b0 + 2);  mma_f16(acc1[1][1], a1, b0 + 2);
                mma_f16(acc1[0][2], a0, b1r);     mma_f16(acc1[1][2], a1, b1r);
                mma_f16(acc1[0][3], a0, b1r + 2); mma_f16(acc1[1][3], a1, b1r + 2);
            } else {
                uint32_t c0[4], c1v[4];
                ldsm4(c0, stgb + laneB + 8192);
                ldsm4(c1v, stgb + laneB + 12288);
                mma_f16(acc0[0][0], a0, b0);      mma_f16(acc0[1][0], a1, b0);
                mma_f16(acc0[0][1], a0, b0 + 2);  mma_f16(acc0[1][1], a1, b0 + 2);
                mma_f16(acc0[0][2], a0, b1r);     mma_f16(acc0[1][2], a1, b1r);
                mma_f16(acc0[0][3], a0, b1r + 2); mma_f16(acc0[1][3], a1, b1r + 2);
                mma_f16(acc1[0][0], a0, c0);      mma_f16(acc1[1][0], a1, c0);
                mma_f16(acc1[0][1], a0, c0 + 2);  mma_f16(acc1[1][1], a1, c0 + 2);
                mma_f16(acc1[0][2], a0, c1v);     mma_f16(acc1[1][2], a1, c1v);
                mma_f16(acc1[0][3], a0, c1v + 2); mma_f16(acc1[1][3], a1, c1v + 2);
            }

            // ---- mid-superstep: layer-0 finalize + early h0 barrier arrive ----
            if (i == 7 && s < 256) {
                const int row0 = wm * 32 + (lane >> 2);
                const int colb = 2 * (lane & 3);
#pragma unroll
                for (int mt = 0; mt < 2; mt++)
#pragma unroll
                    for (int nt = 0; nt < 4; nt++) {
                        const int r = wk * 64 + row0 + mt * 16;
                        const int c = nt * 8 + colb;
                        *(float2*)&dmp[r * 36 + c] =
                            make_float2(acc0[mt][nt][0], acc0[mt][nt][1]);
                        *(float2*)&dmp[(r + 8) * 36 + c] =
                            make_float2(acc0[mt][nt][2], acc0[mt][nt][3]);
                    }
                __syncthreads();
                mbar_wait(mb_g0, (uint32_t)(s & 1));
                {
                    float v0[4];
#pragma unroll
                    for (int g = 0; g < 4; g++) {
                        float s0 = 0.f;
#pragma unroll
                        for (int k = 0; k < 8; k++)
                            s0 += dmp[(k * 64 + erow) * 36 + g * 8 + ecw];
                        v0[g] = s0;
                    }
                    float iv = v0[0] + g0f[erow * 32 + ecw];
                    float fv = v0[1] + g0f[erow * 32 + 8 + ecw];
                    float gv = v0[2] + g0f[erow * 32 + 16 + ecw];
                    float ov = v0[3] + g0f[erow * 32 + 24 + ecw];
                    float cn = sigf(fv) * c0r + sigf(iv) * tanhf_(gv);
                    c0r = cn;
                    g_h0h[(s + 1) & 1][physH] = __float2half_rn(sigf(ov) * tanhf_(cn));
                }
                __syncthreads();
                if (tid == 0) {
                    __threadfence();
                    atomicAdd(&g_bar0, 1u);
                    if (s < 255) fillG0(s + 1);
                }
            }
        }

        // ---- end of superstep: layer-1 finalize + h1 barrier arrive ----
        {
            const int row0 = wm * 32 + (lane >> 2);
            const int colb = 2 * (lane & 3);
#pragma unroll
            for (int mt = 0; mt < 2; mt++)
#pragma unroll
                for (int nt = 0; nt < 4; nt++) {
                    const int r = wk * 64 + row0 + mt * 16;
                    const int c = nt * 8 + colb;
                    *(float2*)&dmp[r * 36 + c] =
                        make_float2(acc1[mt][nt][0], acc1[mt][nt][1]);
                    *(float2*)&dmp[(r + 8) * 36 + c] =
                        make_float2(acc1[mt][nt][2], acc1[mt][nt][3]);
                }
        }
        __syncthreads();
        if (s >= 1) {
            float v1[4];
#pragma unroll
            for (int g = 0; g < 4; g++) {
                float s1 = 0.f;
#pragma unroll
                for (int k = 0; k < 8; k++)
                    s1 += dmp[(k * 64 + erow) * 36 + g * 8 + ecw];
                v1[g] = s1;
            }
            float iv = v1[0] + __ldg(&g_b1p[bn * 32 + ecw]);
            float fv = v1[1] + __ldg(&g_b1p[bn * 32 + 8 + ecw]);
            float gv = v1[2] + __ldg(&g_b1p[bn * 32 + 16 + ecw]);
            float ov = v1[3] + __ldg(&g_b1p[bn * 32 + 24 + ecw]);
            float cn = sigf(fv) * c1r + sigf(iv) * tanhf_(gv);
            c1r = cn;
            float h = sigf(ov) * tanhf_(cn);
            g_h1h[s & 1][physH] = __float2half_rn(h);
            g_h1e[erow * HH + bn * 8 + ecw] = h;
        }
        __syncthreads();
        if (tid == 0 && s < 256) {
            __threadfence();
            atomicAdd(&g_bar1, 1u);
        }
    }
}

__global__ void copy_out_kernel(float* __restrict__ out) {
    int i = blockIdx.x * blockDim.x + threadIdx.x;
    if (i < BB * HH) out[i] = g_h1e[i];
}

// ---------------- launch ----------------
extern "C" void kernel_launch(void* const* d_in, const int* in_sizes, int n_in,
                              void* d_out, int out_size) {
    const float* x   = (const float*)d_in[0];
    const float* Wx0 = (const float*)d_in[1];
    const float* Wh0 = (const float*)d_in[2];
    const float* b0  = (const float*)d_in[3];
    const float* Wx1 = (const float*)d_in[4];
    const float* Wh1 = (const float*)d_in[5];
    const float* b1  = (const float*)d_in[6];
    (void)in_sizes; (void)n_in; (void)out_size;

    cudaFuncSetAttribute(lstm_persist, cudaFuncAttributeMaxDynamicSharedMemorySize, SMEM_BYTES);
    cudaFuncSetAttribute(xgemm_kernel, cudaFuncAttributeMaxDynamicSharedMemorySize, XSMEM);

    convert_pack_kernel<<<4096, 256>>>(x, Wx0, Wh0, Wx1, Wh1, b1);
    init_kernel<<<256, 256>>>();

    dim3 grid_x(G4 / 64, (BB * TT) / 128);
    xgemm_kernel<<<grid_x, 256, XSMEM>>>(b0);

    lstm_persist<<<NB, 512, SMEM_BYTES>>>();

    copy_out_kernel<<<(BB * HH + 255) / 256, 256>>>((float*)d_out);
}

// round 13
// speedup vs baseline: 1.0662x; 1.0662x over previous
#include <cuda_runtime.h>
#include <cuda_fp16.h>
#include <cstdint>
#include <cstddef>

#define BB   64
#define TT   256
#define DD   1024
#define HH   1024
#define G4   4096
#define NB   128

// ---------------- device scratch ----------------
__device__ __align__(256) __half g_G0p[(size_t)TT * NB * 64 * 32]; // [t][bn][row64][gate8*4] fp16
__device__ __align__(256) __half g_Xh[(size_t)BB * TT * DD];       // fp16 X, row-major
__device__ __align__(256) __half g_Wx0h[DD * G4];                  // fp16 col-major [col][k]
__device__ __align__(256) __half g_Wh0h[HH * G4];    // fp16 swizzled tiles [bn][ii8][col32][kin128]
__device__ __align__(256) __half g_Wx1h[HH * G4];
__device__ __align__(256) __half g_Wh1h[HH * G4];
__device__ float  g_b1p[NB * 32];
__device__ __align__(256) __half g_h0h[2][BB * HH];  // fp16 swizzled k-tiles [ii8][row64][kin128]
__device__ __align__(256) __half g_h1h[2][BB * HH];
__device__ float  g_h1e[BB * HH];
__device__ unsigned g_bar0;   // h0-ready arrivals
__device__ unsigned g_bar1;   // h1-ready arrivals

// ---------------- smem layout (bytes) ----------------
// 4 stages x 32768 | dump 73728 | G0 8192 (4096 used) | mbars
#define STAGE_SZ  32768
#define NSTG      4
#define DUMP_OFF  131072
#define G0_OFF    204800
#define MB_OFF    212992
#define SMEM_BYTES 213248

// ---------------- helpers ----------------
__device__ __forceinline__ void mma_f16(float* d, const uint32_t* a, const uint32_t* b) {
    asm volatile(
        "mma.sync.aligned.m16n8k16.row.col.f32.f16.f16.f32 "
        "{%0,%1,%2,%3}, {%4,%5,%6,%7}, {%8,%9}, {%0,%1,%2,%3};"
        : "+f"(d[0]), "+f"(d[1]), "+f"(d[2]), "+f"(d[3])
        : "r"(a[0]), "r"(a[1]), "r"(a[2]), "r"(a[3]), "r"(b[0]), "r"(b[1]));
}
__device__ __forceinline__ void ldsm4(uint32_t* r, uint32_t addr) {
    asm volatile("ldmatrix.sync.aligned.m8n8.x4.shared.b16 {%0,%1,%2,%3}, [%4];"
        : "=r"(r[0]), "=r"(r[1]), "=r"(r[2]), "=r"(r[3]) : "r"(addr));
}
__device__ __forceinline__ void cp16(uint32_t s, const void* g) {
    asm volatile("cp.async.cg.shared.global [%0], [%1], 16;" :: "r"(s), "l"(g));
}
#define CP_COMMIT() asm volatile("cp.async.commit_group;")
#define CP_WAIT1()  asm volatile("cp.async.wait_group 1;")

__device__ __forceinline__ void mbar_init(uint32_t a, uint32_t cnt) {
    asm volatile("mbarrier.init.shared.b64 [%0], %1;" :: "r"(a), "r"(cnt) : "memory");
}
__device__ __forceinline__ void mbar_expect(uint32_t a, uint32_t tx) {
    asm volatile("mbarrier.arrive.expect_tx.shared.b64 _, [%0], %1;" :: "r"(a), "r"(tx) : "memory");
}
__device__ __forceinline__ void mbar_arrive(uint32_t a) {
    asm volatile("mbarrier.arrive.release.cta.shared::cta.b64 _, [%0];" :: "r"(a) : "memory");
}
__device__ __forceinline__ void bulkcp(uint32_t dst, const void* src, uint32_t sz, uint32_t mb) {
    asm volatile(
        "cp.async.bulk.shared::cluster.global.mbarrier::complete_tx::bytes [%0], [%1], %2, [%3];"
        :: "r"(dst), "l"(src), "r"(sz), "r"(mb) : "memory");
}
__device__ __forceinline__ void mbar_wait(uint32_t a, uint32_t par) {
    asm volatile(
        "{\n\t.reg .pred P;\n\tWAIT%=:\n\t"
        "mbarrier.try_wait.parity.acquire.cta.shared::cta.b64 P, [%0], %1;\n\t"
        "@!P bra WAIT%=;\n\t}"
        :: "r"(a), "r"(par) : "memory");
}

__device__ __forceinline__ float sigf(float x)   { return 1.f / (1.f + __expf(-x)); }
__device__ __forceinline__ float tanhf_(float x) { return 2.f / (1.f + __expf(-2.f * x)) - 1.f; }

// ---------------- convert + pack ----------------
__global__ void convert_pack_kernel(const float* __restrict__ x,
                                    const float* __restrict__ Wx0, const float* __restrict__ Wh0,
                                    const float* __restrict__ Wx1, const float* __restrict__ Wh1,
                                    const float* __restrict__ b1) {
    const int n1 = 1 << 22;
    const int stride = gridDim.x * blockDim.x;
    for (int idx = blockIdx.x * blockDim.x + threadIdx.x; idx < 4 * n1; idx += stride) {
        int w = idx >> 22;
        int d = idx & (n1 - 1);
        if (w == 0) {
            int k = d & 1023, col = d >> 10;
            g_Wx0h[d] = __float2half_rn(Wx0[(size_t)k * G4 + col]);  // col-major
        } else {
            int kin = d & 127, col = (d >> 7) & 31, ii = (d >> 12) & 7, bq = d >> 15;
            int gate = col >> 3, cw = col & 7;
            int k = ii * 128 + kin;
            int src = k * G4 + gate * HH + bq * 8 + cw;
            float v = (w == 1) ? Wh0[src] : (w == 2) ? Wx1[src] : Wh1[src];
            uint32_t off = (uint32_t)col * 256 + (uint32_t)kin * 2;
            uint32_t sw = off ^ ((off >> 4) & 0x70);
            __half* dst = (w == 1) ? g_Wh0h : (w == 2) ? g_Wx1h : g_Wh1h;
            dst[(size_t)(bq * 8 + ii) * 4096 + (sw >> 1)] = __float2half_rn(v);
        }
    }
    for (size_t i = blockIdx.x * blockDim.x + threadIdx.x; i < (size_t)BB * TT * DD; i += stride)
        g_Xh[i] = __float2half_rn(x[i]);
    for (int i = blockIdx.x * blockDim.x + threadIdx.x; i < NB * 32; i += stride) {
        int bn = i >> 5, c = i & 31, gate = c >> 3, cw = c & 7;
        g_b1p[i] = b1[gate * HH + bn * 8 + cw];
    }
}

__global__ void init_kernel() {
    int i = blockIdx.x * blockDim.x + threadIdx.x;
    if (i < BB * HH) {
        g_h0h[0][i] = __float2half(0.f); g_h0h[1][i] = __float2half(0.f);
        g_h1h[0][i] = __float2half(0.f); g_h1h[1][i] = __float2half(0.f);
    }
    if (i == 0) { g_bar0 = 0u; g_bar1 = 0u; }
}

// ---------------- precompute G0 = X @ Wx0 + b0 (fp16 HMMA, fp16 out) ----------------
#define XSTAGE 15360
#define XSMEM  (3 * XSTAGE)

__global__ void __launch_bounds__(256, 2) xgemm_kernel(const float* __restrict__ b0) {
    extern __shared__ float xsm[];
    uint32_t sb = (uint32_t)__cvta_generic_to_shared(xsm);
    const int tid = threadIdx.x, lane = tid & 31, warp = tid >> 5;
    const int wm = warp & 3, wn = warp >> 2;
    const int bm = blockIdx.y * 128;
    const int bn = blockIdx.x * 64;

    uint32_t dstA[2], srcA[2];
#pragma unroll
    for (int j = 0; j < 2; j++) {
        int c = j * 256 + tid, row = c >> 2, kc = c & 3;
        dstA[j] = row * 80u + kc * 16u;
        srcA[j] = (uint32_t)((bm + row) * 2048 + kc * 16);
    }
    uint32_t dstB, srcB;
    {
        int col = tid >> 2, kc = tid & 3;
        dstB = 10240u + col * 80u + kc * 16u;
        srcB = (uint32_t)((bn + col) * 2048 + kc * 16);
    }
    const uint32_t laneoffA = (wm * 32 + (lane & 15)) * 80u + (lane >> 4) * 16u;
    const uint32_t laneoffB = 10240u + (wn * 32 + ((lane >> 4) << 3) + (lane & 7)) * 80u
                              + ((lane >> 3) & 1) * 16u;

    auto issue = [&](int st, int k0) {
        const uint32_t stb = sb + st * XSTAGE;
        const char* xb = (const char*)g_Xh + (size_t)k0 * 2;
        const char* wb = (const char*)g_Wx0h + (size_t)k0 * 2;
#pragma unroll
        for (int j = 0; j < 2; j++) cp16(stb + dstA[j], xb + srcA[j]);
        cp16(stb + dstB, wb + srcB);
    };

    float acc[2][4][4];
#pragma unroll
    for (int m = 0; m < 2; m++)
#pragma unroll
        for (int n = 0; n < 4; n++)
#pragma unroll
            for (int p = 0; p < 4; p++) acc[m][n][p] = 0.f;

    issue(0, 0); CP_COMMIT();
    issue(1, 32); CP_COMMIT();

    int st = 0, st2 = 2;
    for (int it = 0; it < 32; it++) {
        CP_WAIT1();
        __syncthreads();
        if (it + 2 < 32) issue(st2, (it + 2) * 32);
        CP_COMMIT();

        const uint32_t base = sb + st * XSTAGE;
#pragma unroll
        for (int ks = 0; ks < 2; ks++) {
            uint32_t a0[4], a1[4], b01[4], b23[4];
            ldsm4(a0, base + laneoffA + ks * 32);
            ldsm4(a1, base + laneoffA + 1280 + ks * 32);
            ldsm4(b01, base + laneoffB + ks * 32);
            ldsm4(b23, base + laneoffB + 1280 + ks * 32);
            mma_f16(acc[0][0], a0, b01);     mma_f16(acc[1][0], a1, b01);
            mma_f16(acc[0][1], a0, b01 + 2); mma_f16(acc[1][1], a1, b01 + 2);
            mma_f16(acc[0][2], a0, b23);     mma_f16(acc[1][2], a1, b23);
            mma_f16(acc[0][3], a0, b23 + 2); mma_f16(acc[1][3], a1, b23 + 2);
        }
        st = (st == 2) ? 0 : st + 1;
        st2 = (st2 == 2) ? 0 : st2 + 1;
    }

#pragma unroll
    for (int mt = 0; mt < 2; mt++)
#pragma unroll
        for (int nt = 0; nt < 4; nt++)
#pragma unroll
            for (int p = 0; p < 4; p++) {
                int row = bm + wm * 32 + mt * 16 + (lane >> 2) + ((p & 2) ? 8 : 0);
                int col = bn + wn * 32 + nt * 8 + 2 * (lane & 3) + (p & 1);
                int b_ = row >> 8;
                int t_ = row & 255;
                int gate = col >> 10, within = col & 1023;
                int bnp = within >> 3, cwi = within & 7;
                g_G0p[(((size_t)t_ * NB + bnp) * 64 + b_) * 32 + gate * 8 + cwi] =
                    __float2half_rn(acc[mt][nt][p] + __ldg(&b0[col]));
            }
}

// ---------------- persistent merged recurrence (free-running warps) ----------------
__global__ void __launch_bounds__(512, 1) lstm_persist() {
    extern __shared__ float sm[];
    uint32_t sb = (uint32_t)__cvta_generic_to_shared(sm);
    const int tid = threadIdx.x, lane = tid & 31, warp = tid >> 5;
    const int wk = warp & 7, wm = warp >> 3;
    const int bn = blockIdx.x;
    const int erow = tid >> 3, ecw = tid & 7;

    const uint32_t mb_full = sb + MB_OFF;                 // 4 x 8B
    const uint32_t mb_g0   = sb + MB_OFF + 32;            // 8B
    const uint32_t mb_emp  = sb + MB_OFF + 40;            // 4 x 8B
    if (tid == 0) {
#pragma unroll
        for (int i = 0; i < NSTG; i++) { mbar_init(mb_full + i * 8, 2); mbar_init(mb_emp + i * 8, 16); }
        mbar_init(mb_g0, 1);
    }
    __syncthreads();

    // ldmatrix lane offsets (swizzled, 256B row stride, k-window = wk*32 bytes)
    const uint32_t kbA = (uint32_t)wk * 32 + (uint32_t)(lane >> 4) * 16;
    const uint32_t laneA = (uint32_t)(wm * 32 + (lane & 15)) * 256
                           + (kbA ^ (((uint32_t)lane & 7) << 4));
    const uint32_t kbB = (uint32_t)wk * 32 + (uint32_t)((lane >> 3) & 1) * 16;
    const uint32_t laneB = 16384u + (uint32_t)(((lane >> 4) << 3) + (lane & 7)) * 256
                           + (kbB ^ (((uint32_t)lane & 7) << 4));

    const char* W0base = (const char*)g_Wh0h + (size_t)bn * 65536;
    const char* W1base = (const char*)g_Wx1h + (size_t)bn * 65536;
    const char* W2base = (const char*)g_Wh1h + (size_t)bn * 65536;

    auto fillB = [&](int st, int fi) {
        const uint32_t mb = mb_full + st * 8;
        const int seg = fi >> 3, ii = fi & 7;
        const uint32_t d = sb + st * STAGE_SZ + 16384;
        if (seg) {
            mbar_expect(mb, 8192);
            bulkcp(d, W2base + ii * 8192, 8192, mb);
        } else {
            mbar_expect(mb, 16384);
            bulkcp(d,        W0base + ii * 8192, 8192, mb);
            bulkcp(d + 8192, W1base + ii * 8192, 8192, mb);
        }
    };
    auto fillA = [&](int st, int fi, const char* A0p, const char* A1p) {
        const uint32_t mb = mb_full + st * 8;
        const int seg = fi >> 3, ii = fi & 7;
        const char* src = (seg ? A1p : A0p) + ii * 16384;
        const uint32_t d = sb + st * STAGE_SZ;
        mbar_expect(mb, 16384);
        bulkcp(d,        src,        8192, mb);
        bulkcp(d + 8192, src + 8192, 8192, mb);
    };
    auto fillG0 = [&](int t) {
        mbar_expect(mb_g0, 4096);
        bulkcp(sb + G0_OFF, (const char*)g_G0p + ((size_t)t * NB + bn) * 4096, 4096, mb_g0);
    };

    // epilogue h-store swizzled address
    const int iiH = bn >> 4;
    const int kinH = (bn & 15) * 8 + ecw;
    const uint32_t offH = (uint32_t)erow * 256 + (uint32_t)kinH * 2;
    const uint32_t swH = offH ^ ((offH >> 4) & 0x70);
    const int physH = iiH * 8192 + (int)(swH >> 1);

    float* dmp = sm + (DUMP_OFF >> 2);
    const __half* g0h = (const __half*)(sm + (G0_OFF >> 2));

    float c0r = 0.f, c1r = 0.f;
    unsigned pb = 0;   // full-barrier phase bits (per warp, identical)
    unsigned eb = 0;   // empty-barrier phase bits (tid0 only)

    // initial fills: iters 0-2 (stages 0-2) + G0(0); stage fills skip empty-wait (never consumed)
    if (tid == 0) {
        const char* A0i = (const char*)g_h0h[0];
        fillG0(0);
#pragma unroll
        for (int j = 0; j < 3; j++) { fillA(j, j, A0i, A0i); fillB(j, j); }
    }

    for (int s = 0; s <= 256; s++) {
        const char* A0 = (const char*)g_h0h[s & 1];
        const char* A1 = (const char*)g_h1h[(s + 1) & 1];
        const char* A0n = (const char*)g_h0h[(s + 1) & 1];

        float acc0[2][4][4], acc1[2][4][4];
#pragma unroll
        for (int m = 0; m < 2; m++)
#pragma unroll
            for (int n = 0; n < 4; n++)
#pragma unroll
                for (int p = 0; p < 4; p++) { acc0[m][n][p] = 0.f; acc1[m][n][p] = 0.f; }

#pragma unroll
        for (int i = 0; i < 16; i++) {
            const int stc = i & 3;
            mbar_wait(mb_full + stc * 8, (pb >> stc) & 1);
            pb ^= 1u << stc;

            if (tid == 0) {
                if (i == 5 && s > 0) {   // gate A1 fills on h1[s] from all blocks
                    while (*(volatile unsigned*)&g_bar1 < (unsigned)s * NB) {}
                    __threadfence();
                }
                const int ft = i + 3;
                const int stf = ft & 3;
                if (ft < 16) {
                    if (!(s == 0 && i == 0)) {           // stage 3's first-ever fill skips
                        mbar_wait(mb_emp + stf * 8, (eb >> stf) & 1);
                        eb ^= 1u << stf;
                    }
                    fillA(stf, ft, A0, A1);
                    fillB(stf, ft);
                } else if (s < 256) {
                    if (i == 13) {       // gate next-superstep A0 fills on h0[s+1]
                        while (*(volatile unsigned*)&g_bar0 < (unsigned)(s + 1) * NB) {}
                        __threadfence();
                    }
                    mbar_wait(mb_emp + stf * 8, (eb >> stf) & 1);
                    eb ^= 1u << stf;
                    fillA(stf, ft - 16, A0n, A0n);       // ft-16 in 0..2 => seg0
                    fillB(stf, ft - 16);
                }
            }

            const uint32_t stgb = sb + stc * STAGE_SZ;
            const int seg = i >> 3;
            uint32_t a0[4], a1[4], b0[4], b1r[4];
            ldsm4(a0, stgb + laneA);
            ldsm4(a1, stgb + laneA + 4096);
            ldsm4(b0, stgb + laneB);
            ldsm4(b1r, stgb + laneB + 4096);
            if (seg) {
                if (lane == 0) mbar_arrive(mb_emp + stc * 8);   // done reading stage
                mma_f16(acc1[0][0], a0, b0);      mma_f16(acc1[1][0], a1, b0);
                mma_f16(acc1[0][1], a0, b0 + 2);  mma_f16(acc1[1][1], a1, b0 + 2);
                mma_f16(acc1[0][2], a0, b1r);     mma_f16(acc1[1][2], a1, b1r);
                mma_f16(acc1[0][3], a0, b1r + 2); mma_f16(acc1[1][3], a1, b1r + 2);
            } else {
                uint32_t c0[4], c1v[4];
                ldsm4(c0, stgb + laneB + 8192);
                ldsm4(c1v, stgb + laneB + 12288);
                if (lane == 0) mbar_arrive(mb_emp + stc * 8);   // done reading stage
                mma_f16(acc0[0][0], a0, b0);      mma_f16(acc0[1][0], a1, b0);
                mma_f16(acc0[0][1], a0, b0 + 2);  mma_f16(acc0[1][1], a1, b0 + 2);
                mma_f16(acc0[0][2], a0, b1r);     mma_f16(acc0[1][2], a1, b1r);
                mma_f16(acc0[0][3], a0, b1r + 2); mma_f16(acc0[1][3], a1, b1r + 2);
                mma_f16(acc1[0][0], a0, c0);      mma_f16(acc1[1][0], a1, c0);
                mma_f16(acc1[0][1], a0, c0 + 2);  mma_f16(acc1[1][1], a1, c0 + 2);
                mma_f16(acc1[0][2], a0, c1v);     mma_f16(acc1[1][2], a1, c1v);
                mma_f16(acc1[0][3], a0, c1v + 2); mma_f16(acc1[1][3], a1, c1v + 2);
            }

            // ---- mid-superstep: layer-0 finalize + early h0 barrier arrive ----
            if (i == 7 && s < 256) {
                const int row0 = wm * 32 + (lane >> 2);
                const int colb = 2 * (lane & 3);
#pragma unroll
                for (int mt = 0; mt < 2; mt++)
#pragma unroll
                    for (int nt = 0; nt < 4; nt++) {
                        const int r = wk * 64 + row0 + mt * 16;
                        const int c = nt * 8 + colb;
                        *(float2*)&dmp[r * 36 + c] =
                            make_float2(acc0[mt][nt][0], acc0[mt][nt][1]);
                        *(float2*)&dmp[(r + 8) * 36 + c] =
                            make_float2(acc0[mt][nt][2], acc0[mt][nt][3]);
                    }
                __syncthreads();
                mbar_wait(mb_g0, (uint32_t)(s & 1));
                {
                    float v0[4];
#pragma unroll
                    for (int g = 0; g < 4; g++) {
                        float s0 = 0.f;
#pragma unroll
                        for (int k = 0; k < 8; k++)
                            s0 += dmp[(k * 64 + erow) * 36 + g * 8 + ecw];
                        v0[g] = s0;
                    }
                    float iv = v0[0] + __half2float(g0h[erow * 32 + ecw]);
                    float fv = v0[1] + __half2float(g0h[erow * 32 + 8 + ecw]);
                    float gv = v0[2] + __half2float(g0h[erow * 32 + 16 + ecw]);
                    float ov = v0[3] + __half2float(g0h[erow * 32 + 24 + ecw]);
                    float cn = sigf(fv) * c0r + sigf(iv) * tanhf_(gv);
                    c0r = cn;
                    g_h0h[(s + 1) & 1][physH] = __float2half_rn(sigf(ov) * tanhf_(cn));
                }
                __syncthreads();
                if (tid == 0) {
                    __threadfence();
                    atomicAdd(&g_bar0, 1u);
                    if (s < 255) fillG0(s + 1);
                }
            }
        }

        // ---- end of superstep: layer-1 finalize + h1 barrier arrive ----
        {
            const int row0 = wm * 32 + (lane >> 2);
            const int colb = 2 * (lane & 3);
#pragma unroll
            for (int mt = 0; mt < 2; mt++)
#pragma unroll
                for (int nt = 0; nt < 4; nt++) {
                    const int r = wk * 64 + row0 + mt * 16;
                    const int c = nt * 8 + colb;
                    *(float2*)&dmp[r * 36 + c] =
                        make_float2(acc1[mt][nt][0], acc1[mt][nt][1]);
                    *(float2*)&dmp[(r + 8) * 36 + c] =
                        make_float2(acc1[mt][nt][2], acc1[mt][nt][3]);
                }
        }
        __syncthreads();
        if (s >= 1) {
            float v1[4];
#pragma unroll
            for (int g = 0; g < 4; g++) {
                float s1 = 0.f;
#pragma unroll
                for (int k = 0; k < 8; k++)
                    s1 += dmp[(k * 64 + erow) * 36 + g * 8 + ecw];
                v1[g] = s1;
            }
            float iv = v1[0] + __ldg(&g_b1p[bn * 32 + ecw]);
            float fv = v1[1] + __ldg(&g_b1p[bn * 32 + 8 + ecw]);
            float gv = v1[2] + __ldg(&g_b1p[bn * 32 + 16 + ecw]);
            float ov = v1[3] + __ldg(&g_b1p[bn * 32 + 24 + ecw]);
            float cn = sigf(fv) * c1r + sigf(iv) * tanhf_(gv);
            c1r = cn;
            float h = sigf(ov) * tanhf_(cn);
            g_h1h[s & 1][physH] = __float2half_rn(h);
            g_h1e[erow * HH + bn * 8 + ecw] = h;
        }
        __syncthreads();
        if (tid == 0 && s < 256) {
            __threadfence();
            atomicAdd(&g_bar1, 1u);
        }
    }
}

__global__ void copy_out_kernel(float* __restrict__ out) {
    int i = blockIdx.x * blockDim.x + threadIdx.x;
    if (i < BB * HH) out[i] = g_h1e[i];
}

// ---------------- launch ----------------
extern "C" void kernel_launch(void* const* d_in, const int* in_sizes, int n_in,
                              void* d_out, int out_size) {
    const float* x   = (const float*)d_in[0];
    const float* Wx0 = (const float*)d_in[1];
    const float* Wh0 = (const float*)d_in[2];
    const float* b0  = (const float*)d_in[3];
    const float* Wx1 = (const float*)d_in[4];
    const float* Wh1 = (const float*)d_in[5];
    const float* b1  = (const float*)d_in[6];
    (void)in_sizes; (void)n_in; (void)out_size;

    cudaFuncSetAttribute(lstm_persist, cudaFuncAttributeMaxDynamicSharedMemorySize, SMEM_BYTES);
    cudaFuncSetAttribute(xgemm_kernel, cudaFuncAttributeMaxDynamicSharedMemorySize, XSMEM);

    convert_pack_kernel<<<4096, 256>>>(x, Wx0, Wh0, Wx1, Wh1, b1);
    init_kernel<<<256, 256>>>();

    dim3 grid_x(G4 / 64, (BB * TT) / 128);
    xgemm_kernel<<<grid_x, 256, XSMEM>>>(b0);

    lstm_persist<<<NB, 512, SMEM_BYTES>>>();

    copy_out_kernel<<<(BB * HH + 255) / 256, 256>>>((float*)d_out);
}

// round 16
// speedup vs baseline: 1.1247x; 1.0549x over previous
#include <cuda_runtime.h>
#include <cuda_fp16.h>
#include <cstdint>
#include <cstddef>

#define BB   64
#define TT   256
#define DD   1024
#define HH   1024
#define G4   4096
#define NB   128

// ---------------- device scratch ----------------
__device__ __align__(256) __half g_G0p[(size_t)TT * NB * 64 * 32]; // [t][bn][row64][gate8*4] fp16
__device__ __align__(256) __half g_Xh[(size_t)BB * TT * DD];       // fp16 X, row-major
__device__ __align__(256) __half g_Wx0h[DD * G4];                  // fp16 col-major [col][k]
__device__ __align__(256) __half g_Wh0h[HH * G4];    // fp16 swizzled tiles [bn][ii8][col32][kin128]
__device__ __align__(256) __half g_Wx1h[HH * G4];
__device__ __align__(256) __half g_Wh1h[HH * G4];
__device__ float  g_b1p[NB * 32];
__device__ __align__(256) __half g_h0h[2][BB * HH];  // fp16 swizzled k-tiles [ii8][row64][kin128]
__device__ __align__(256) __half g_h1h[2][BB * HH];
__device__ unsigned g_bar0;   // h0-ready arrivals
__device__ unsigned g_bar1;   // h1-ready arrivals

// ---------------- smem layout (bytes) ----------------
// 4 stages x 24576 (A 16384 | B 8192) | resident Wx1 65536 | dump 36864 | G0 4096 | mbars
#define STAGE_SZ  24576
#define NSTG      4
#define BS_OFF    16384
#define WX1_OFF   98304
#define DUMP_OFF  163840
#define G0_OFF    200704
#define MB_OFF    204800
#define SMEM_BYTES 205056
// mbars: full[4]@+0, g0@+32, emp[4]@+40, res@+72

// ---------------- helpers ----------------
__device__ __forceinline__ void mma_f16(float* d, const uint32_t* a, const uint32_t* b) {
    asm volatile(
        "mma.sync.aligned.m16n8k16.row.col.f32.f16.f16.f32 "
        "{%0,%1,%2,%3}, {%4,%5,%6,%7}, {%8,%9}, {%0,%1,%2,%3};"
        : "+f"(d[0]), "+f"(d[1]), "+f"(d[2]), "+f"(d[3])
        : "r"(a[0]), "r"(a[1]), "r"(a[2]), "r"(a[3]), "r"(b[0]), "r"(b[1]));
}
__device__ __forceinline__ void ldsm4(uint32_t* r, uint32_t addr) {
    asm volatile("ldmatrix.sync.aligned.m8n8.x4.shared.b16 {%0,%1,%2,%3}, [%4];"
        : "=r"(r[0]), "=r"(r[1]), "=r"(r[2]), "=r"(r[3]) : "r"(addr));
}
__device__ __forceinline__ void cp16(uint32_t s, const void* g) {
    asm volatile("cp.async.cg.shared.global [%0], [%1], 16;" :: "r"(s), "l"(g));
}
#define CP_COMMIT() asm volatile("cp.async.commit_group;")
#define CP_WAIT1()  asm volatile("cp.async.wait_group 1;")

__device__ __forceinline__ void mbar_init(uint32_t a, uint32_t cnt) {
    asm volatile("mbarrier.init.shared.b64 [%0], %1;" :: "r"(a), "r"(cnt) : "memory");
}
__device__ __forceinline__ void mbar_expect(uint32_t a, uint32_t tx) {
    asm volatile("mbarrier.arrive.expect_tx.shared.b64 _, [%0], %1;" :: "r"(a), "r"(tx) : "memory");
}
__device__ __forceinline__ void mbar_arrive(uint32_t a) {
    asm volatile("mbarrier.arrive.release.cta.shared::cta.b64 _, [%0];" :: "r"(a) : "memory");
}
__device__ __forceinline__ void bulkcp(uint32_t dst, const void* src, uint32_t sz, uint32_t mb) {
    asm volatile(
        "cp.async.bulk.shared::cluster.global.mbarrier::complete_tx::bytes [%0], [%1], %2, [%3];"
        :: "r"(dst), "l"(src), "r"(sz), "r"(mb) : "memory");
}
__device__ __forceinline__ void mbar_wait(uint32_t a, uint32_t par) {
    asm volatile(
        "{\n\t.reg .pred P;\n\tWAIT%=:\n\t"
        "mbarrier.try_wait.parity.acquire.cta.shared::cta.b64 P, [%0], %1;\n\t"
        "@!P bra WAIT%=;\n\t}"
        :: "r"(a), "r"(par) : "memory");
}

__device__ __forceinline__ float sigf(float x)   { return 1.f / (1.f + __expf(-x)); }
__device__ __forceinline__ float tanhf_(float x) { return 2.f / (1.f + __expf(-2.f * x)) - 1.f; }

// ---------------- convert + pack ----------------
__global__ void convert_pack_kernel(const float* __restrict__ x,
                                    const float* __restrict__ Wx0, const float* __restrict__ Wh0,
                                    const float* __restrict__ Wx1, const float* __restrict__ Wh1,
                                    const float* __restrict__ b1) {
    const int n1 = 1 << 22;
    const int stride = gridDim.x * blockDim.x;
    for (int idx = blockIdx.x * blockDim.x + threadIdx.x; idx < 4 * n1; idx += stride) {
        int w = idx >> 22;
        int d = idx & (n1 - 1);
        if (w == 0) {
            int k = d & 1023, col = d >> 10;
            g_Wx0h[d] = __float2half_rn(Wx0[(size_t)k * G4 + col]);  // col-major
        } else {
            int kin = d & 127, col = (d >> 7) & 31, ii = (d >> 12) & 7, bq = d >> 15;
            int gate = col >> 3, cw = col & 7;
            int k = ii * 128 + kin;
            int src = k * G4 + gate * HH + bq * 8 + cw;
            float v = (w == 1) ? Wh0[src] : (w == 2) ? Wx1[src] : Wh1[src];
            uint32_t off = (uint32_t)col * 256 + (uint32_t)kin * 2;
            uint32_t sw = off ^ ((off >> 4) & 0x70);
            __half* dst = (w == 1) ? g_Wh0h : (w == 2) ? g_Wx1h : g_Wh1h;
            dst[(size_t)(bq * 8 + ii) * 4096 + (sw >> 1)] = __float2half_rn(v);
        }
    }
    for (size_t i = blockIdx.x * blockDim.x + threadIdx.x; i < (size_t)BB * TT * DD; i += stride)
        g_Xh[i] = __float2half_rn(x[i]);
    for (int i = blockIdx.x * blockDim.x + threadIdx.x; i < NB * 32; i += stride) {
        int bn = i >> 5, c = i & 31, gate = c >> 3, cw = c & 7;
        g_b1p[i] = b1[gate * HH + bn * 8 + cw];
    }
}

__global__ void init_kernel() {
    int i = blockIdx.x * blockDim.x + threadIdx.x;
    if (i < BB * HH) {
        g_h0h[0][i] = __float2half(0.f); g_h0h[1][i] = __float2half(0.f);
        g_h1h[0][i] = __float2half(0.f); g_h1h[1][i] = __float2half(0.f);
    }
    if (i == 0) { g_bar0 = 0u; g_bar1 = 0u; }
}

// ---------------- precompute G0 = X @ Wx0 + b0 (fp16 HMMA, fp16 out) ----------------
#define XSTAGE 15360
#define XSMEM  (3 * XSTAGE)

__global__ void __launch_bounds__(256, 2) xgemm_kernel(const float* __restrict__ b0) {
    extern __shared__ float xsm[];
    uint32_t sb = (uint32_t)__cvta_generic_to_shared(xsm);
    const int tid = threadIdx.x, lane = tid & 31, warp = tid >> 5;
    const int wm = warp & 3, wn = warp >> 2;
    const int bm = blockIdx.y * 128;
    const int bn = blockIdx.x * 64;

    uint32_t dstA[2], srcA[2];
#pragma unroll
    for (int j = 0; j < 2; j++) {
        int c = j * 256 + tid, row = c >> 2, kc = c & 3;
        dstA[j] = row * 80u + kc * 16u;
        srcA[j] = (uint32_t)((bm + row) * 2048 + kc * 16);
    }
    uint32_t dstB, srcB;
    {
        int col = tid >> 2, kc = tid & 3;
        dstB = 10240u + col * 80u + kc * 16u;
        srcB = (uint32_t)((bn + col) * 2048 + kc * 16);
    }
    const uint32_t laneoffA = (wm * 32 + (lane & 15)) * 80u + (lane >> 4) * 16u;
    const uint32_t laneoffB = 10240u + (wn * 32 + ((lane >> 4) << 3) + (lane & 7)) * 80u
                              + ((lane >> 3) & 1) * 16u;

    auto issue = [&](int st, int k0) {
        const uint32_t stb = sb + st * XSTAGE;
        const char* xb = (const char*)g_Xh + (size_t)k0 * 2;
        const char* wb = (const char*)g_Wx0h + (size_t)k0 * 2;
#pragma unroll
        for (int j = 0; j < 2; j++) cp16(stb + dstA[j], xb + srcA[j]);
        cp16(stb + dstB, wb + srcB);
    };

    float acc[2][4][4];
#pragma unroll
    for (int m = 0; m < 2; m++)
#pragma unroll
        for (int n = 0; n < 4; n++)
#pragma unroll
            for (int p = 0; p < 4; p++) acc[m][n][p] = 0.f;

    issue(0, 0); CP_COMMIT();
    issue(1, 32); CP_COMMIT();

    int st = 0, st2 = 2;
    for (int it = 0; it < 32; it++) {
        CP_WAIT1();
        __syncthreads();
        if (it + 2 < 32) issue(st2, (it + 2) * 32);
        CP_COMMIT();

        const uint32_t base = sb + st * XSTAGE;
#pragma unroll
        for (int ks = 0; ks < 2; ks++) {
            uint32_t a0[4], a1[4], b01[4], b23[4];
            ldsm4(a0, base + laneoffA + ks * 32);
            ldsm4(a1, base + laneoffA + 1280 + ks * 32);
            ldsm4(b01, base + laneoffB + ks * 32);
            ldsm4(b23, base + laneoffB + 1280 + ks * 32);
            mma_f16(acc[0][0], a0, b01);     mma_f16(acc[1][0], a1, b01);
            mma_f16(acc[0][1], a0, b01 + 2); mma_f16(acc[1][1], a1, b01 + 2);
            mma_f16(acc[0][2], a0, b23);     mma_f16(acc[1][2], a1, b23);
            mma_f16(acc[0][3], a0, b23 + 2); mma_f16(acc[1][3], a1, b23 + 2);
        }
        st = (st == 2) ? 0 : st + 1;
        st2 = (st2 == 2) ? 0 : st2 + 1;
    }

#pragma unroll
    for (int mt = 0; mt < 2; mt++)
#pragma unroll
        for (int nt = 0; nt < 4; nt++)
#pragma unroll
            for (int p = 0; p < 4; p++) {
                int row = bm + wm * 32 + mt * 16 + (lane >> 2) + ((p & 2) ? 8 : 0);
                int col = bn + wn * 32 + nt * 8 + 2 * (lane & 3) + (p & 1);
                int b_ = row >> 8;
                int t_ = row & 255;
                int gate = col >> 10, within = col & 1023;
                int bnp = within >> 3, cwi = within & 7;
                g_G0p[(((size_t)t_ * NB + bnp) * 64 + b_) * 32 + gate * 8 + cwi] =
                    __float2half_rn(acc[mt][nt][p] + __ldg(&b0[col]));
            }
}

// ---------------- persistent recurrence: resident Wx1, wk4 x wn2 x wm2 ----------------
__global__ void __launch_bounds__(512, 1) lstm_persist(float* __restrict__ out) {
    extern __shared__ float sm[];
    uint32_t sb = (uint32_t)__cvta_generic_to_shared(sm);
    const int tid = threadIdx.x, lane = tid & 31, warp = tid >> 5;
    const int wk = warp & 3, wn = (warp >> 2) & 1, wm = warp >> 3;
    const int bn = blockIdx.x;
    const int erow = tid >> 3, ecw = tid & 7;

    const uint32_t mbF   = sb + MB_OFF;          // full[4], count=1
    const uint32_t mbG   = sb + MB_OFF + 32;     // g0, count=1
    const uint32_t mbEmp = sb + MB_OFF + 40;     // empty[4], count=16
    const uint32_t mbR   = sb + MB_OFF + 72;     // resident, count=1
    if (tid == 0) {
#pragma unroll
        for (int i = 0; i < NSTG; i++) { mbar_init(mbF + i * 8, 1); mbar_init(mbEmp + i * 8, 16); }
        mbar_init(mbG, 1); mbar_init(mbR, 1);
    }
    __syncthreads();

    // ldmatrix lane offsets — XOR applied to the FULL k-offset per kstep (R9 pattern)
    const uint32_t swz = ((uint32_t)lane & 7) << 4;
    const uint32_t rowA = (uint32_t)(wm * 32 + (lane & 15));
    const uint32_t colB = (uint32_t)(wn * 16 + ((lane >> 4) << 3) + (lane & 7));
    uint32_t laneA[2], laneB[2], laneW[2];
#pragma unroll
    for (int ks = 0; ks < 2; ks++) {
        const uint32_t ka = (uint32_t)wk * 64 + (uint32_t)(lane >> 4) * 16 + (uint32_t)ks * 32;
        const uint32_t kb = (uint32_t)wk * 64 + (uint32_t)((lane >> 3) & 1) * 16 + (uint32_t)ks * 32;
        laneA[ks] = rowA * 256 + (ka ^ swz);
        laneB[ks] = BS_OFF + colB * 256 + (kb ^ swz);
        laneW[ks] = colB * 256 + (kb ^ swz);
    }

    const char* W0base = (const char*)g_Wh0h + (size_t)bn * 65536;
    const char* W2base = (const char*)g_Wh1h + (size_t)bn * 65536;

    // fill: A 16KB + streamed B 8KB, uniform expect
    auto fill = [&](int st, int fi, const char* A0p, const char* A1p) {
        const uint32_t mb = mbF + st * 8;
        const int seg = fi >> 3, ii = fi & 7;
        mbar_expect(mb, 24576);
        bulkcp(sb + st * STAGE_SZ, (seg ? A1p : A0p) + ii * 16384, 16384, mb);
        bulkcp(sb + st * STAGE_SZ + BS_OFF,
               (seg ? W2base : W0base) + ii * 8192, 8192, mb);
    };
    auto fillG0 = [&](int t) {
        mbar_expect(mbG, 4096);
        bulkcp(sb + G0_OFF, (const char*)g_G0p + ((size_t)t * NB + bn) * 4096, 4096, mbG);
    };

    // epilogue h-store swizzled address (one element per thread)
    const int iiH = bn >> 4;
    const int kinH = (bn & 15) * 8 + ecw;
    const uint32_t offH_ = (uint32_t)erow * 256 + (uint32_t)kinH * 2;
    const uint32_t swH = offH_ ^ ((offH_ >> 4) & 0x70);
    const int physH = iiH * 8192 + (int)(swH >> 1);

    float* dmp = sm + (DUMP_OFF >> 2);
    const __half* g0h = (const __half*)(sm + (G0_OFF >> 2));

    float c0r = 0.f, c1r = 0.f;
    unsigned pb = 0;   // full phase bits (all threads)
    unsigned eb = 0;   // empty phase bits (tid0)

    // initial: resident Wx1 (64KB, contiguous per bn) + G0(0) + stages 0-2
    if (tid == 0) {
        mbar_expect(mbR, 65536);
        bulkcp(sb + WX1_OFF, (const char*)g_Wx1h + (size_t)bn * 65536, 65536, mbR);
        fillG0(0);
        const char* A0i = (const char*)g_h0h[0];
#pragma unroll
        for (int j = 0; j < 3; j++) fill(j, j, A0i, A0i);
    }
    mbar_wait(mbR, 0);   // all threads: resident ready before first MMA

    for (int s = 0; s <= 256; s++) {
        const char* A0 = (const char*)g_h0h[s & 1];
        const char* A1 = (const char*)g_h1h[(s + 1) & 1];
        const char* A0n = (const char*)g_h0h[(s + 1) & 1];

        float acc0[2][2][4], acc1[2][2][4];
#pragma unroll
        for (int n = 0; n < 2; n++)
#pragma unroll
            for (int m = 0; m < 2; m++)
#pragma unroll
                for (int p = 0; p < 4; p++) { acc0[n][m][p] = 0.f; acc1[n][m][p] = 0.f; }

#pragma unroll
        for (int i = 0; i < 16; i++) {
            const int stc = i & 3;
            mbar_wait(mbF + stc * 8, (pb >> stc) & 1);
            pb ^= 1u << stc;

            if (tid == 0) {
                const int ft = i + 3;
                const int stf = ft & 3;
                if (ft < 16) {
                    if (!(s == 0 && i == 0)) {
                        mbar_wait(mbEmp + stf * 8, (eb >> stf) & 1);
                        eb ^= 1u << stf;
                    }
                    if (ft == 8 && s > 0) {       // gate A1 fills on h1[s] from all blocks
                        while (*(volatile unsigned*)&g_bar1 < (unsigned)s * NB) {}
                        __threadfence();
                    }
                    fill(stf, ft, A0, A1);
                } else if (s < 256) {
                    if (i == 13) {                // gate next-superstep A0 fills on h0[s+1]
                        while (*(volatile unsigned*)&g_bar0 < (unsigned)(s + 1) * NB) {}
                        __threadfence();
                    }
                    mbar_wait(mbEmp + stf * 8, (eb >> stf) & 1);
                    eb ^= 1u << stf;
                    fill(stf, ft - 16, A0n, A0n); // ft-16 in 0..2 => seg0
                }
            }

            const uint32_t stgb = sb + stc * STAGE_SZ;
            const int seg = i >> 3;
            uint32_t a0[2][4], a1[2][4], b0[2][4];
#pragma unroll
            for (int ks = 0; ks < 2; ks++) {
                ldsm4(a0[ks], stgb + laneA[ks]);
                ldsm4(a1[ks], stgb + laneA[ks] + 4096);
                ldsm4(b0[ks], stgb + laneB[ks]);
            }
            if (lane == 0) mbar_arrive(mbEmp + stc * 8);   // done reading stage

            if (!seg) {
                const uint32_t wxb = sb + WX1_OFF + (uint32_t)(i & 7) * 8192u;
#pragma unroll
                for (int ks = 0; ks < 2; ks++) {
                    uint32_t w0[4];
                    ldsm4(w0, wxb + laneW[ks]);
                    mma_f16(acc0[0][0], a0[ks], b0[ks]);     mma_f16(acc0[0][1], a1[ks], b0[ks]);
                    mma_f16(acc0[1][0], a0[ks], b0[ks] + 2); mma_f16(acc0[1][1], a1[ks], b0[ks] + 2);
                    mma_f16(acc1[0][0], a0[ks], w0);         mma_f16(acc1[0][1], a1[ks], w0);
                    mma_f16(acc1[1][0], a0[ks], w0 + 2);     mma_f16(acc1[1][1], a1[ks], w0 + 2);
                }
            } else {
#pragma unroll
                for (int ks = 0; ks < 2; ks++) {
                    mma_f16(acc1[0][0], a0[ks], b0[ks]);     mma_f16(acc1[0][1], a1[ks], b0[ks]);
                    mma_f16(acc1[1][0], a0[ks], b0[ks] + 2); mma_f16(acc1[1][1], a1[ks], b0[ks] + 2);
                }
            }

            // ---- mid-superstep: layer-0 finalize + early h0 barrier arrive ----
            if (i == 7 && s < 256) {
                const int row0 = wm * 32 + (lane >> 2);
                const int colb = wn * 16 + 2 * (lane & 3);
#pragma unroll
                for (int nt = 0; nt < 2; nt++)
#pragma unroll
                    for (int mt = 0; mt < 2; mt++) {
                        const int r = wk * 64 + row0 + mt * 16;
                        const int c = colb + nt * 8;
                        *(float2*)&dmp[r * 36 + c] =
                            make_float2(acc0[nt][mt][0], acc0[nt][mt][1]);
                        *(float2*)&dmp[(r + 8) * 36 + c] =
                            make_float2(acc0[nt][mt][2], acc0[nt][mt][3]);
                    }
                __syncthreads();
                mbar_wait(mbG, (uint32_t)(s & 1));
                {
                    float v0[4];
#pragma unroll
                    for (int g = 0; g < 4; g++) {
                        float s0 = 0.f;
#pragma unroll
                        for (int k = 0; k < 4; k++)
                            s0 += dmp[(k * 64 + erow) * 36 + g * 8 + ecw];
                        v0[g] = s0;
                    }
                    float iv = v0[0] + __half2float(g0h[erow * 32 + ecw]);
                    float fv = v0[1] + __half2float(g0h[erow * 32 + 8 + ecw]);
                    float gv = v0[2] + __half2float(g0h[erow * 32 + 16 + ecw]);
                    float ov = v0[3] + __half2float(g0h[erow * 32 + 24 + ecw]);
                    float cn = sigf(fv) * c0r + sigf(iv) * tanhf_(gv);
                    c0r = cn;
                    g_h0h[(s + 1) & 1][physH] = __float2half_rn(sigf(ov) * tanhf_(cn));
                }
                __syncthreads();
                if (tid == 0) {
                    __threadfence();
                    atomicAdd(&g_bar0, 1u);
                    if (s < 255) fillG0(s + 1);
                }
            }
        }

        // ---- end of superstep: layer-1 finalize + h1 barrier arrive ----
        {
            const int row0 = wm * 32 + (lane >> 2);
            const int colb = wn * 16 + 2 * (lane & 3);
#pragma unroll
            for (int nt = 0; nt < 2; nt++)
#pragma unroll
                for (int mt = 0; mt < 2; mt++) {
                    const int r = wk * 64 + row0 + mt * 16;
                    const int c = colb + nt * 8;
                    *(float2*)&dmp[r * 36 + c] =
                        make_float2(acc1[nt][mt][0], acc1[nt][mt][1]);
                    *(float2*)&dmp[(r + 8) * 36 + c] =
                        make_float2(acc1[nt][mt][2], acc1[nt][mt][3]);
                }
        }
        __syncthreads();
        if (s >= 1) {
            float v1[4];
#pragma unroll
            for (int g = 0; g < 4; g++) {
                float s1 = 0.f;
#pragma unroll
                for (int k = 0; k < 4; k++)
                    s1 += dmp[(k * 64 + erow) * 36 + g * 8 + ecw];
                v1[g] = s1;
            }
            float iv = v1[0] + __ldg(&g_b1p[bn * 32 + ecw]);
            float fv = v1[1] + __ldg(&g_b1p[bn * 32 + 8 + ecw]);
            float gv = v1[2] + __ldg(&g_b1p[bn * 32 + 16 + ecw]);
            float ov = v1[3] + __ldg(&g_b1p[bn * 32 + 24 + ecw]);
            float cn = sigf(fv) * c1r + sigf(iv) * tanhf_(gv);
            c1r = cn;
            float h = sigf(ov) * tanhf_(cn);
            if (s < 256) g_h1h[s & 1][physH] = __float2half_rn(h);
            else         out[erow * HH + bn * 8 + ecw] = h;   // final output
        }
        __syncthreads();
        if (tid == 0 && s < 256) {
            __threadfence();
            atomicAdd(&g_bar1, 1u);
        }
    }
}

// ---------------- launch ----------------
extern "C" void kernel_launch(void* const* d_in, const int* in_sizes, int n_in,
                              void* d_out, int out_size) {
    const float* x   = (const float*)d_in[0];
    const float* Wx0 = (const float*)d_in[1];
    const float* Wh0 = (const float*)d_in[2];
    const float* b0  = (const float*)d_in[3];
    const float* Wx1 = (const float*)d_in[4];
    const float* Wh1 = (const float*)d_in[5];
    const float* b1  = (const float*)d_in[6];
    (void)in_sizes; (void)n_in; (void)out_size;

    cudaFuncSetAttribute(lstm_persist, cudaFuncAttributeMaxDynamicSharedMemorySize, SMEM_BYTES);
    cudaFuncSetAttribute(xgemm_kernel, cudaFuncAttributeMaxDynamicSharedMemorySize, XSMEM);

    convert_pack_kernel<<<4096, 256>>>(x, Wx0, Wh0, Wx1, Wh1, b1);
    init_kernel<<<256, 256>>>();

    dim3 grid_x(G4 / 64, (BB * TT) / 128);
    xgemm_kernel<<<grid_x, 256, XSMEM>>>(b0);

    lstm_persist<<<NB, 512, SMEM_BYTES>>>((float*)d_out);
}

// round 17
// speedup vs baseline: 1.4156x; 1.2587x over previous
#include <cuda_runtime.h>
#include <cuda_fp16.h>
#include <cstdint>
#include <cstddef>

#define BB   64
#define TT   256
#define DD   1024
#define HH   1024
#define G4   4096
#define NB   128

// ---------------- device scratch ----------------
__device__ __align__(256) __half g_G0p[(size_t)TT * NB * 64 * 32]; // [t][bn][row64][gate8*4] fp16
__device__ __align__(256) __half g_Xh[(size_t)BB * TT * DD];       // fp16 X, row-major
__device__ __align__(256) __half g_Wx0h[DD * G4];                  // fp16 col-major [col][k]
__device__ __align__(256) __half g_Wh0h[HH * G4];    // fp16 swizzled tiles [bn][ii8][col32][kin128]
__device__ __align__(256) __half g_Wx1h[HH * G4];
__device__ __align__(256) __half g_Wh1h[HH * G4];
__device__ float  g_b1p[NB * 32];
__device__ __align__(256) __half g_h0h[2][BB * HH];  // fp16 swizzled k-tiles [ii8][row64][kin128]
__device__ __align__(256) __half g_h1h[2][BB * HH];
__device__ unsigned g_bar0;   // h0-ready arrivals
__device__ unsigned g_bar1;   // h1-ready arrivals

// ---------------- smem layout (bytes) ----------------
#define STAGE_SZ  24576
#define NSTG      4
#define BS_OFF    16384
#define WX1_OFF   98304
#define DUMP_OFF  163840
#define G0_OFF    200704
#define MB_OFF    204800
#define SMEM_BYTES 205056
// mbars: full[4]@+0, g0@+32, emp[4]@+40, res@+72

// ---------------- helpers ----------------
__device__ __forceinline__ void mma_f16(float* d, const uint32_t* a, const uint32_t* b) {
    asm volatile(
        "mma.sync.aligned.m16n8k16.row.col.f32.f16.f16.f32 "
        "{%0,%1,%2,%3}, {%4,%5,%6,%7}, {%8,%9}, {%0,%1,%2,%3};"
        : "+f"(d[0]), "+f"(d[1]), "+f"(d[2]), "+f"(d[3])
        : "r"(a[0]), "r"(a[1]), "r"(a[2]), "r"(a[3]), "r"(b[0]), "r"(b[1]));
}
__device__ __forceinline__ void ldsm4(uint32_t* r, uint32_t addr) {
    asm volatile("ldmatrix.sync.aligned.m8n8.x4.shared.b16 {%0,%1,%2,%3}, [%4];"
        : "=r"(r[0]), "=r"(r[1]), "=r"(r[2]), "=r"(r[3]) : "r"(addr));
}
__device__ __forceinline__ void cp16(uint32_t s, const void* g) {
    asm volatile("cp.async.cg.shared.global [%0], [%1], 16;" :: "r"(s), "l"(g));
}
#define CP_COMMIT() asm volatile("cp.async.commit_group;")
#define CP_WAIT1()  asm volatile("cp.async.wait_group 1;")
#define BAR_COMPUTE() asm volatile("bar.sync 1, 512;" ::: "memory")

__device__ __forceinline__ void mbar_init(uint32_t a, uint32_t cnt) {
    asm volatile("mbarrier.init.shared.b64 [%0], %1;" :: "r"(a), "r"(cnt) : "memory");
}
__device__ __forceinline__ void mbar_expect(uint32_t a, uint32_t tx) {
    asm volatile("mbarrier.arrive.expect_tx.shared.b64 _, [%0], %1;" :: "r"(a), "r"(tx) : "memory");
}
__device__ __forceinline__ void mbar_arrive(uint32_t a) {
    asm volatile("mbarrier.arrive.release.cta.shared::cta.b64 _, [%0];" :: "r"(a) : "memory");
}
__device__ __forceinline__ void bulkcp(uint32_t dst, const void* src, uint32_t sz, uint32_t mb) {
    asm volatile(
        "cp.async.bulk.shared::cluster.global.mbarrier::complete_tx::bytes [%0], [%1], %2, [%3];"
        :: "r"(dst), "l"(src), "r"(sz), "r"(mb) : "memory");
}
__device__ __forceinline__ void mbar_wait(uint32_t a, uint32_t par) {
    asm volatile(
        "{\n\t.reg .pred P;\n\tWAIT%=:\n\t"
        "mbarrier.try_wait.parity.acquire.cta.shared::cta.b64 P, [%0], %1;\n\t"
        "@!P bra WAIT%=;\n\t}"
        :: "r"(a), "r"(par) : "memory");
}

__device__ __forceinline__ float sigf(float x)   { return 1.f / (1.f + __expf(-x)); }
__device__ __forceinline__ float tanhf_(float x) { return 2.f / (1.f + __expf(-2.f * x)) - 1.f; }

// ---------------- convert + pack ----------------
__global__ void convert_pack_kernel(const float* __restrict__ x,
                                    const float* __restrict__ Wx0, const float* __restrict__ Wh0,
                                    const float* __restrict__ Wx1, const float* __restrict__ Wh1,
                                    const float* __restrict__ b1) {
    const int n1 = 1 << 22;
    const int stride = gridDim.x * blockDim.x;
    for (int idx = blockIdx.x * blockDim.x + threadIdx.x; idx < 4 * n1; idx += stride) {
        int w = idx >> 22;
        int d = idx & (n1 - 1);
        if (w == 0) {
            int k = d & 1023, col = d >> 10;
            g_Wx0h[d] = __float2half_rn(Wx0[(size_t)k * G4 + col]);  // col-major
        } else {
            int kin = d & 127, col = (d >> 7) & 31, ii = (d >> 12) & 7, bq = d >> 15;
            int gate = col >> 3, cw = col & 7;
            int k = ii * 128 + kin;
            int src = k * G4 + gate * HH + bq * 8 + cw;
            float v = (w == 1) ? Wh0[src] : (w == 2) ? Wx1[src] : Wh1[src];
            uint32_t off = (uint32_t)col * 256 + (uint32_t)kin * 2;
            uint32_t sw = off ^ ((off >> 4) & 0x70);
            __half* dst = (w == 1) ? g_Wh0h : (w == 2) ? g_Wx1h : g_Wh1h;
            dst[(size_t)(bq * 8 + ii) * 4096 + (sw >> 1)] = __float2half_rn(v);
        }
    }
    for (size_t i = blockIdx.x * blockDim.x + threadIdx.x; i < (size_t)BB * TT * DD; i += stride)
        g_Xh[i] = __float2half_rn(x[i]);
    for (int i = blockIdx.x * blockDim.x + threadIdx.x; i < NB * 32; i += stride) {
        int bn = i >> 5, c = i & 31, gate = c >> 3, cw = c & 7;
        g_b1p[i] = b1[gate * HH + bn * 8 + cw];
    }
}

__global__ void init_kernel() {
    int i = blockIdx.x * blockDim.x + threadIdx.x;
    if (i < BB * HH) {
        g_h0h[0][i] = __float2half(0.f); g_h0h[1][i] = __float2half(0.f);
        g_h1h[0][i] = __float2half(0.f); g_h1h[1][i] = __float2half(0.f);
    }
    if (i == 0) { g_bar0 = 0u; g_bar1 = 0u; }
}

// ---------------- precompute G0 = X @ Wx0 + b0 (fp16 HMMA, fp16 out) ----------------
#define XSTAGE 15360
#define XSMEM  (3 * XSTAGE)

__global__ void __launch_bounds__(256, 2) xgemm_kernel(const float* __restrict__ b0) {
    extern __shared__ float xsm[];
    uint32_t sb = (uint32_t)__cvta_generic_to_shared(xsm);
    const int tid = threadIdx.x, lane = tid & 31, warp = tid >> 5;
    const int wm = warp & 3, wn = warp >> 2;
    const int bm = blockIdx.y * 128;
    const int bn = blockIdx.x * 64;

    uint32_t dstA[2], srcA[2];
#pragma unroll
    for (int j = 0; j < 2; j++) {
        int c = j * 256 + tid, row = c >> 2, kc = c & 3;
        dstA[j] = row * 80u + kc * 16u;
        srcA[j] = (uint32_t)((bm + row) * 2048 + kc * 16);
    }
    uint32_t dstB, srcB;
    {
        int col = tid >> 2, kc = tid & 3;
        dstB = 10240u + col * 80u + kc * 16u;
        srcB = (uint32_t)((bn + col) * 2048 + kc * 16);
    }
    const uint32_t laneoffA = (wm * 32 + (lane & 15)) * 80u + (lane >> 4) * 16u;
    const uint32_t laneoffB = 10240u + (wn * 32 + ((lane >> 4) << 3) + (lane & 7)) * 80u
                              + ((lane >> 3) & 1) * 16u;

    auto issue = [&](int st, int k0) {
        const uint32_t stb = sb + st * XSTAGE;
        const char* xb = (const char*)g_Xh + (size_t)k0 * 2;
        const char* wb = (const char*)g_Wx0h + (size_t)k0 * 2;
#pragma unroll
        for (int j = 0; j < 2; j++) cp16(stb + dstA[j], xb + srcA[j]);
        cp16(stb + dstB, wb + srcB);
    };

    float acc[2][4][4];
#pragma unroll
    for (int m = 0; m < 2; m++)
#pragma unroll
        for (int n = 0; n < 4; n++)
#pragma unroll
            for (int p = 0; p < 4; p++) acc[m][n][p] = 0.f;

    issue(0, 0); CP_COMMIT();
    issue(1, 32); CP_COMMIT();

    int st = 0, st2 = 2;
    for (int it = 0; it < 32; it++) {
        CP_WAIT1();
        __syncthreads();
        if (it + 2 < 32) issue(st2, (it + 2) * 32);
        CP_COMMIT();

        const uint32_t base = sb + st * XSTAGE;
#pragma unroll
        for (int ks = 0; ks < 2; ks++) {
            uint32_t a0[4], a1[4], b01[4], b23[4];
            ldsm4(a0, base + laneoffA + ks * 32);
            ldsm4(a1, base + laneoffA + 1280 + ks * 32);
            ldsm4(b01, base + laneoffB + ks * 32);
            ldsm4(b23, base + laneoffB + 1280 + ks * 32);
            mma_f16(acc[0][0], a0, b01);     mma_f16(acc[1][0], a1, b01);
            mma_f16(acc[0][1], a0, b01 + 2); mma_f16(acc[1][1], a1, b01 + 2);
            mma_f16(acc[0][2], a0, b23);     mma_f16(acc[1][2], a1, b23);
            mma_f16(acc[0][3], a0, b23 + 2); mma_f16(acc[1][3], a1, b23 + 2);
        }
        st = (st == 2) ? 0 : st + 1;
        st2 = (st2 == 2) ? 0 : st2 + 1;
    }

#pragma unroll
    for (int mt = 0; mt < 2; mt++)
#pragma unroll
        for (int nt = 0; nt < 4; nt++)
#pragma unroll
            for (int p = 0; p < 4; p++) {
                int row = bm + wm * 32 + mt * 16 + (lane >> 2) + ((p & 2) ? 8 : 0);
                int col = bn + wn * 32 + nt * 8 + 2 * (lane & 3) + (p & 1);
                int b_ = row >> 8;
                int t_ = row & 255;
                int gate = col >> 10, within = col & 1023;
                int bnp = within >> 3, cwi = within & 7;
                g_G0p[(((size_t)t_ * NB + bnp) * 64 + b_) * 32 + gate * 8 + cwi] =
                    __float2half_rn(acc[mt][nt][p] + __ldg(&b0[col]));
            }
}

// ---------------- persistent recurrence: producer warp + 16 compute warps ----------------
__global__ void __launch_bounds__(544, 1) lstm_persist(float* __restrict__ out) {
    extern __shared__ float sm[];
    uint32_t sb = (uint32_t)__cvta_generic_to_shared(sm);
    const int tid = threadIdx.x, lane = tid & 31, warp = tid >> 5;
    const int bn = blockIdx.x;

    const uint32_t mbF   = sb + MB_OFF;          // full[4], count=1
    const uint32_t mbG   = sb + MB_OFF + 32;     // g0, count=1
    const uint32_t mbEmp = sb + MB_OFF + 40;     // empty[4], count=16
    const uint32_t mbR   = sb + MB_OFF + 72;     // resident, count=1
    if (tid == 0) {
#pragma unroll
        for (int i = 0; i < NSTG; i++) { mbar_init(mbF + i * 8, 1); mbar_init(mbEmp + i * 8, 16); }
        mbar_init(mbG, 1); mbar_init(mbR, 1);
    }
    __syncthreads();   // all 544 threads

    const char* W0base = (const char*)g_Wh0h + (size_t)bn * 65536;
    const char* W2base = (const char*)g_Wh1h + (size_t)bn * 65536;

    auto fill = [&](int st, int fi, const char* A0p, const char* A1p) {
        const uint32_t mb = mbF + st * 8;
        const int seg = fi >> 3, ii = fi & 7;
        mbar_expect(mb, 24576);
        bulkcp(sb + st * STAGE_SZ, (seg ? A1p : A0p) + ii * 16384, 16384, mb);
        bulkcp(sb + st * STAGE_SZ + BS_OFF,
               (seg ? W2base : W0base) + ii * 8192, 8192, mb);
    };
    auto fillG0 = [&](int t) {
        mbar_expect(mbG, 4096);
        bulkcp(sb + G0_OFF, (const char*)g_G0p + ((size_t)t * NB + bn) * 4096, 4096, mbG);
    };

    // ================= PRODUCER WARP (warp 16) =================
    if (warp == 16) {
        if (lane == 0) {
            // resident Wx1 + G0(0) + initial stage fills
            mbar_expect(mbR, 65536);
            bulkcp(sb + WX1_OFF, (const char*)g_Wx1h + (size_t)bn * 65536, 65536, mbR);
            fillG0(0);
            const char* A0i = (const char*)g_h0h[0];
#pragma unroll
            for (int j = 0; j < 3; j++) fill(j, j, A0i, A0i);

            unsigned ebp = 0;
            bool first = true;
            for (int s = 0; s <= 256; s++) {
                const char* A0 = (const char*)g_h0h[s & 1];
                const char* A1 = (const char*)g_h1h[(s + 1) & 1];
                const char* A0n = (const char*)g_h0h[(s + 1) & 1];
                for (int i = 0; i < 16; i++) {
                    const int ft = i + 3;
                    const int stf = ft & 3;
                    if (ft < 16) {
                        if (!first) {
                            mbar_wait(mbEmp + stf * 8, (ebp >> stf) & 1);
                            ebp ^= 1u << stf;
                        }
                        first = false;
                        if (ft == 8 && s > 0) {   // gate A1 fills on h1[s] from all blocks
                            while (*(volatile unsigned*)&g_bar1 < (unsigned)s * NB) {}
                            __threadfence();
                        }
                        fill(stf, ft, A0, A1);
                    } else if (s < 256) {
                        if (i == 13) {            // gate next-superstep A0 fills on h0[s+1]
                            while (*(volatile unsigned*)&g_bar0 < (unsigned)(s + 1) * NB) {}
                            __threadfence();
                        }
                        mbar_wait(mbEmp + stf * 8, (ebp >> stf) & 1);
                        ebp ^= 1u << stf;
                        fill(stf, ft - 16, A0n, A0n);   // ft-16 in 0..2 => seg0
                    }
                }
            }
        }
        return;   // whole producer warp exits compute path
    }

    // ================= COMPUTE WARPS (0..15) =================
    const int wk = warp & 3, wn = (warp >> 2) & 1, wm = warp >> 3;
    const int erow = tid >> 3, ecw = tid & 7;

    // ldmatrix lane offsets — XOR applied to the FULL k-offset per kstep
    const uint32_t swz = ((uint32_t)lane & 7) << 4;
    const uint32_t rowA = (uint32_t)(wm * 32 + (lane & 15));
    const uint32_t colB = (uint32_t)(wn * 16 + ((lane >> 4) << 3) + (lane & 7));
    uint32_t laneA[2], laneB[2], laneW[2];
#pragma unroll
    for (int ks = 0; ks < 2; ks++) {
        const uint32_t ka = (uint32_t)wk * 64 + (uint32_t)(lane >> 4) * 16 + (uint32_t)ks * 32;
        const uint32_t kb = (uint32_t)wk * 64 + (uint32_t)((lane >> 3) & 1) * 16 + (uint32_t)ks * 32;
        laneA[ks] = rowA * 256 + (ka ^ swz);
        laneB[ks] = BS_OFF + colB * 256 + (kb ^ swz);
        laneW[ks] = colB * 256 + (kb ^ swz);
    }

    // epilogue h-store swizzled address (one element per thread)
    const int iiH = bn >> 4;
    const int kinH = (bn & 15) * 8 + ecw;
    const uint32_t offH_ = (uint32_t)erow * 256 + (uint32_t)kinH * 2;
    const uint32_t swH = offH_ ^ ((offH_ >> 4) & 0x70);
    const int physH = iiH * 8192 + (int)(swH >> 1);

    float* dmp = sm + (DUMP_OFF >> 2);
    const __half* g0h = (const __half*)(sm + (G0_OFF >> 2));

    float c0r = 0.f, c1r = 0.f;
    unsigned pb = 0;   // full phase bits

    mbar_wait(mbR, 0);   // resident Wx1 ready before first MMA

    for (int s = 0; s <= 256; s++) {
        float acc0[2][2][4], acc1[2][2][4];
#pragma unroll
        for (int n = 0; n < 2; n++)
#pragma unroll
            for (int m = 0; m < 2; m++)
#pragma unroll
                for (int p = 0; p < 4; p++) { acc0[n][m][p] = 0.f; acc1[n][m][p] = 0.f; }

#pragma unroll
        for (int i = 0; i < 16; i++) {
            const int stc = i & 3;
            mbar_wait(mbF + stc * 8, (pb >> stc) & 1);
            pb ^= 1u << stc;

            const uint32_t stgb = sb + stc * STAGE_SZ;
            const int seg = i >> 3;
            uint32_t a0[2][4], a1[2][4], b0[2][4];
#pragma unroll
            for (int ks = 0; ks < 2; ks++) {
                ldsm4(a0[ks], stgb + laneA[ks]);
                ldsm4(a1[ks], stgb + laneA[ks] + 4096);
                ldsm4(b0[ks], stgb + laneB[ks]);
            }
            if (lane == 0) mbar_arrive(mbEmp + stc * 8);   // done reading stage

            if (!seg) {
                const uint32_t wxb = sb + WX1_OFF + (uint32_t)(i & 7) * 8192u;
#pragma unroll
                for (int ks = 0; ks < 2; ks++) {
                    uint32_t w0[4];
                    ldsm4(w0, wxb + laneW[ks]);
                    mma_f16(acc0[0][0], a0[ks], b0[ks]);     mma_f16(acc0[0][1], a1[ks], b0[ks]);
                    mma_f16(acc0[1][0], a0[ks], b0[ks] + 2); mma_f16(acc0[1][1], a1[ks], b0[ks] + 2);
                    mma_f16(acc1[0][0], a0[ks], w0);         mma_f16(acc1[0][1], a1[ks], w0);
                    mma_f16(acc1[1][0], a0[ks], w0 + 2);     mma_f16(acc1[1][1], a1[ks], w0 + 2);
                }
            } else {
#pragma unroll
                for (int ks = 0; ks < 2; ks++) {
                    mma_f16(acc1[0][0], a0[ks], b0[ks]);     mma_f16(acc1[0][1], a1[ks], b0[ks]);
                    mma_f16(acc1[1][0], a0[ks], b0[ks] + 2); mma_f16(acc1[1][1], a1[ks], b0[ks] + 2);
                }
            }

            // ---- mid-superstep: layer-0 finalize + early h0 barrier arrive ----
            if (i == 7 && s < 256) {
                const int row0 = wm * 32 + (lane >> 2);
                const int colb = wn * 16 + 2 * (lane & 3);
#pragma unroll
                for (int nt = 0; nt < 2; nt++)
#pragma unroll
                    for (int mt = 0; mt < 2; mt++) {
                        const int r = wk * 64 + row0 + mt * 16;
                        const int c = colb + nt * 8;
                        *(float2*)&dmp[r * 36 + c] =
                            make_float2(acc0[nt][mt][0], acc0[nt][mt][1]);
                        *(float2*)&dmp[(r + 8) * 36 + c] =
                            make_float2(acc0[nt][mt][2], acc0[nt][mt][3]);
                    }
                BAR_COMPUTE();
                mbar_wait(mbG, (uint32_t)(s & 1));
                {
                    float v0[4];
#pragma unroll
                    for (int g = 0; g < 4; g++) {
                        float s0 = 0.f;
#pragma unroll
                        for (int k = 0; k < 4; k++)
                            s0 += dmp[(k * 64 + erow) * 36 + g * 8 + ecw];
                        v0[g] = s0;
                    }
                    float iv = v0[0] + __half2float(g0h[erow * 32 + ecw]);
                    float fv = v0[1] + __half2float(g0h[erow * 32 + 8 + ecw]);
                    float gv = v0[2] + __half2float(g0h[erow * 32 + 16 + ecw]);
                    float ov = v0[3] + __half2float(g0h[erow * 32 + 24 + ecw]);
                    float cn = sigf(fv) * c0r + sigf(iv) * tanhf_(gv);
                    c0r = cn;
                    g_h0h[(s + 1) & 1][physH] = __float2half_rn(sigf(ov) * tanhf_(cn));
                }
                BAR_COMPUTE();
                if (tid == 0) {
                    __threadfence();
                    atomicAdd(&g_bar0, 1u);
                    if (s < 255) fillG0(s + 1);
                }
            }
        }

        // ---- end of superstep: layer-1 finalize + h1 barrier arrive ----
        {
            const int row0 = wm * 32 + (lane >> 2);
            const int colb = wn * 16 + 2 * (lane & 3);
#pragma unroll
            for (int nt = 0; nt < 2; nt++)
#pragma unroll
                for (int mt = 0; mt < 2; mt++) {
                    const int r = wk * 64 + row0 + mt * 16;
                    const int c = colb + nt * 8;
                    *(float2*)&dmp[r * 36 + c] =
                        make_float2(acc1[nt][mt][0], acc1[nt][mt][1]);
                    *(float2*)&dmp[(r + 8) * 36 + c] =
                        make_float2(acc1[nt][mt][2], acc1[nt][mt][3]);
                }
        }
        BAR_COMPUTE();
        if (s >= 1) {
            float v1[4];
#pragma unroll
            for (int g = 0; g < 4; g++) {
                float s1 = 0.f;
#pragma unroll
                for (int k = 0; k < 4; k++)
                    s1 += dmp[(k * 64 + erow) * 36 + g * 8 + ecw];
                v1[g] = s1;
            }
            float iv = v1[0] + __ldg(&g_b1p[bn * 32 + ecw]);
            float fv = v1[1] + __ldg(&g_b1p[bn * 32 + 8 + ecw]);
            float gv = v1[2] + __ldg(&g_b1p[bn * 32 + 16 + ecw]);
            float ov = v1[3] + __ldg(&g_b1p[bn * 32 + 24 + ecw]);
            float cn = sigf(fv) * c1r + sigf(iv) * tanhf_(gv);
            c1r = cn;
            float h = sigf(ov) * tanhf_(cn);
            if (s < 256) g_h1h[s & 1][physH] = __float2half_rn(h);
            else         out[erow * HH + bn * 8 + ecw] = h;   // final output
        }
        BAR_COMPUTE();
        if (tid == 0 && s < 256) {
            __threadfence();
            atomicAdd(&g_bar1, 1u);
        }
    }
}

// ---------------- launch ----------------
extern "C" void kernel_launch(void* const* d_in, const int* in_sizes, int n_in,
                              void* d_out, int out_size) {
    const float* x   = (const float*)d_in[0];
    const float* Wx0 = (const float*)d_in[1];
    const float* Wh0 = (const float*)d_in[2];
    const float* b0  = (const float*)d_in[3];
    const float* Wx1 = (const float*)d_in[4];
    const float* Wh1 = (const float*)d_in[5];
    const float* b1  = (const float*)d_in[6];
    (void)in_sizes; (void)n_in; (void)out_size;

    cudaFuncSetAttribute(lstm_persist, cudaFuncAttributeMaxDynamicSharedMemorySize, SMEM_BYTES);
    cudaFuncSetAttribute(xgemm_kernel, cudaFuncAttributeMaxDynamicSharedMemorySize, XSMEM);

    convert_pack_kernel<<<4096, 256>>>(x, Wx0, Wh0, Wx1, Wh1, b1);
    init_kernel<<<256, 256>>>();

    dim3 grid_x(G4 / 64, (BB * TT) / 128);
    xgemm_kernel<<<grid_x, 256, XSMEM>>>(b0);

    lstm_persist<<<NB, 544, SMEM_BYTES>>>((float*)d_out);
}